// round 1
// baseline (speedup 1.0000x reference)
#include <cuda_runtime.h>
#include <cstdint>

#define NQ      14
#define NSTATE  (1 << NQ)          // 16384
#define NLAYERS 6
#define NGATES  (NQ + NLAYERS*NQ)  // 98: 14 RX + 84 Rot
#define NPASS   (NGATES/2)         // 49 fused 2-gate passes
#define TPB     512

struct Pass {
    unsigned m1, m2;   // XOR pair masks (columns of L)
    unsigned r1, r2;   // parity masks (rows of L^-1)
    int ha, hb;        // pivot bits for coset enumeration (ha < hb)
    int g1, g2;        // gate matrix indices
};
struct Params {
    Pass p[NPASS];
    unsigned rz;       // parity mask for <Z_0>
};

__device__ __forceinline__ float2 mix(float2 ga, float2 a, float2 gb, float2 b) {
    // ga*a + gb*b (complex), 8 FMA-class ops
    float re = a.x * ga.x;
    re = fmaf(-a.y, ga.y, re);
    re = fmaf( b.x, gb.x, re);
    re = fmaf(-b.y, gb.y, re);
    float im = a.x * ga.y;
    im = fmaf( a.y, ga.x, im);
    im = fmaf( b.x, gb.y, im);
    im = fmaf( b.y, gb.x, im);
    return make_float2(re, im);
}

__global__ void __launch_bounds__(TPB, 1)
qsim_kernel(const float* __restrict__ x, const float* __restrict__ wts,
            float* __restrict__ out, Params P)
{
    extern __shared__ float2 st[];           // 16384 complex amplitudes
    __shared__ float2 gates[NGATES][4];
    __shared__ float  red[TPB / 32];

    const int tid = threadIdx.x;
    const int b   = blockIdx.x;

    // ---- build gate matrices ----
    if (tid < NQ) {
        // RX(x) = [[c, -i s], [-i s, c]], c=cos(x/2), s=sin(x/2)
        float xv = x[b * NQ + tid];
        float s, c;
        sincosf(0.5f * xv, &s, &c);
        gates[tid][0] = make_float2(c, 0.f);
        gates[tid][1] = make_float2(0.f, -s);
        gates[tid][2] = make_float2(0.f, -s);
        gates[tid][3] = make_float2(c, 0.f);
    } else if (tid < NGATES) {
        // Rot(phi,theta,omega) = RZ(omega) RY(theta) RZ(phi)
        int g = tid - NQ;
        int l = g / NQ, w = g % NQ;
        const float* ww = wts + (l * NQ + w) * 3;
        float phi = ww[0], th = ww[1], om = ww[2];
        float stt, ct, sA, cA, sB, cB;
        sincosf(0.5f * th, &stt, &ct);
        sincosf(0.5f * (phi + om), &sA, &cA);
        sincosf(0.5f * (phi - om), &sB, &cB);
        gates[tid][0] = make_float2( cA * ct, -sA * ct);
        gates[tid][1] = make_float2(-cB * stt, -sB * stt);
        gates[tid][2] = make_float2( cB * stt, -sB * stt);
        gates[tid][3] = make_float2( cA * ct,  sA * ct);
    }

    // ---- init |0...0> ----
    for (int i = tid; i < NSTATE; i += TPB)
        st[i] = make_float2(i == 0 ? 1.f : 0.f, 0.f);
    __syncthreads();

    // ---- 49 fused passes (each applies 2 single-qubit gates) ----
    #pragma unroll 1
    for (int ps = 0; ps < NPASS; ps++) {
        const Pass pp = P.p[ps];
        float2 G1[4], G2[4];
        #pragma unroll
        for (int k = 0; k < 4; k++) { G1[k] = gates[pp.g1][k]; G2[k] = gates[pp.g2][k]; }
        const unsigned m1 = pp.m1, m2 = pp.m2, r1 = pp.r1, r2 = pp.r2;
        const int ha = pp.ha, hb = pp.hb;
        const unsigned maskA = (1u << ha) - 1u;
        const unsigned maskB = (1u << hb) - 1u;

        #pragma unroll 2
        for (int q = tid; q < NSTATE / 4; q += TPB) {
            // insert zero bits at ha then hb (ha < hb) -> coset representative
            unsigned t  = ((unsigned(q) >> ha) << (ha + 1)) | (unsigned(q) & maskA);
            unsigned p  = ((t >> hb) << (hb + 1)) | (t & maskB);
            unsigned i0 = p, i1 = p ^ m1, i2 = p ^ m2, i3 = p ^ m1 ^ m2;

            float2 y0 = st[i0], y1 = st[i1], y2 = st[i2], y3 = st[i3];

            // logical bit values of representative p
            int s1 = __popc(p & r1) & 1;
            int s2 = __popc(p & r2) & 1;
            // permute into logical order: y0=a00, y1=a10, y2=a01, y3=a11
            if (s1) { float2 tm = y0; y0 = y1; y1 = tm; tm = y2; y2 = y3; y3 = tm; }
            if (s2) { float2 tm = y0; y0 = y2; y2 = tm; tm = y1; y1 = y3; y3 = tm; }

            // G1 along bit1: pairs (y0,y1) and (y2,y3)
            float2 z0 = mix(G1[0], y0, G1[1], y1);
            float2 z1 = mix(G1[2], y0, G1[3], y1);
            float2 z2 = mix(G1[0], y2, G1[1], y3);
            float2 z3 = mix(G1[2], y2, G1[3], y3);
            // G2 along bit2: pairs (z0,z2) and (z1,z3)
            float2 o0 = mix(G2[0], z0, G2[1], z2);
            float2 o2 = mix(G2[2], z0, G2[3], z2);
            float2 o1 = mix(G2[0], z1, G2[1], z3);
            float2 o3 = mix(G2[2], z1, G2[3], z3);

            // inverse permute back to physical slot order
            if (s2) { float2 tm = o0; o0 = o2; o2 = tm; tm = o1; o1 = o3; o3 = tm; }
            if (s1) { float2 tm = o0; o0 = o1; o1 = tm; tm = o2; o2 = o3; o3 = tm; }

            st[i0] = o0; st[i1] = o1; st[i2] = o2; st[i3] = o3;
        }
        __syncthreads();
    }

    // ---- <Z_0> = sum (-1)^{parity(i & rz)} |amp|^2 ----
    float acc = 0.f;
    const unsigned rz = P.rz;
    for (int i = tid; i < NSTATE; i += TPB) {
        float2 a  = st[i];
        float  pr = fmaf(a.x, a.x, a.y * a.y);
        acc += (__popc(unsigned(i) & rz) & 1) ? -pr : pr;
    }
    #pragma unroll
    for (int off = 16; off; off >>= 1)
        acc += __shfl_down_sync(0xffffffffu, acc, off);
    if ((tid & 31) == 0) red[tid >> 5] = acc;
    __syncthreads();
    if (tid == 0) {
        float s = 0.f;
        #pragma unroll
        for (int wgi = 0; wgi < TPB / 32; wgi++) s += red[wgi];
        out[b] = s;
    }
}

static inline int ctz32(unsigned v) {
#if defined(__GNUC__) || defined(__clang__)
    return __builtin_ctz(v);
#else
    int c = 0; while (!(v & 1u)) { v >>= 1; c++; } return c;
#endif
}

static void fill_pass(Pass& ps, const unsigned* col, const unsigned* row,
                      int w1, int w2, int g1, int g2) {
    ps.m1 = col[w1]; ps.m2 = col[w2];
    ps.r1 = row[w1]; ps.r2 = row[w2];
    int h1 = ctz32(ps.m1);
    unsigned v2 = ps.m2;
    if ((v2 >> h1) & 1u) v2 ^= ps.m1;   // eliminate -> projection onto (h1,h2) invertible
    int h2 = ctz32(v2);
    ps.ha = h1 < h2 ? h1 : h2;
    ps.hb = h1 < h2 ? h2 : h1;
    ps.g1 = g1; ps.g2 = g2;
}

extern "C" void kernel_launch(void* const* d_in, const int* in_sizes, int n_in,
                              void* d_out, int out_size) {
    const float* x   = (const float*)d_in[0];   // (B, 14)
    const float* wts = (const float*)d_in[1];   // (6, 14, 3)
    float*       out = (float*)d_out;           // (B,)
    const int B = in_sizes[0] / NQ;

    // ---- host precompute: GF(2) linear map tracking eliminates all CNOT passes ----
    Params P;
    unsigned col[NQ], row[NQ];
    for (int i = 0; i < NQ; i++) { col[i] = 1u << i; row[i] = 1u << i; }

    int pi = 0;
    // RX encoding passes (identity map)
    for (int k = 0; k < NQ / 2; k++)
        fill_pass(P.p[pi++], col, row, 2 * k, 2 * k + 1, 2 * k, 2 * k + 1);

    for (int l = 0; l < NLAYERS; l++) {
        // Rot passes use masks from CNOTs of previous layers
        for (int k = 0; k < NQ / 2; k++) {
            int w1 = 2 * k, w2 = 2 * k + 1;
            fill_pass(P.p[pi++], col, row, w1, w2,
                      NQ + l * NQ + w1, NQ + l * NQ + w2);
        }
        // absorb this layer's CNOT ring into L:
        // CNOT(c,t): col[c] ^= col[t];  row[t] ^= row[c]
        int r = (l % (NQ - 1)) + 1;
        for (int w = 0; w < NQ; w++) {
            int c = w, t = (w + r) % NQ;
            col[c] ^= col[t];
            row[t] ^= row[c];
        }
    }
    P.rz = row[0];

    cudaFuncSetAttribute(qsim_kernel, cudaFuncAttributeMaxDynamicSharedMemorySize,
                         NSTATE * sizeof(float2));
    qsim_kernel<<<B, TPB, NSTATE * sizeof(float2)>>>(x, wts, out, P);
}

// round 2
// speedup vs baseline: 1.6988x; 1.6988x over previous
#include <cuda_runtime.h>
#include <cstdint>

#define NQ      14
#define NSTATE  (1 << NQ)          // 16384
#define NLAYERS 6
#define NGATES  (NLAYERS * NQ)     // 84 (RX merged into layer-0 Rot)
#define NPASSES (NLAYERS * 4)      // 24: per block 3 quads + 1 pair
#define TPB     512

typedef unsigned long long ull;

struct PassP {
    unsigned cm[16];   // XOR masks for logical nibble j (cm[1<<i] = m_i)
    unsigned r[4];     // parity rows (L^-1)
    int      piv[4];   // sorted pivot bits (ascending); only first nw used
    int      g[4];     // gate ids
    int      nw;       // 4 or 2
};
struct Params {
    PassP p[NPASSES];
    unsigned rz;
};

// ---------------- packed f32x2 helpers ----------------
__device__ __forceinline__ ull pack2(float lo, float hi) {
    ull r; asm("mov.b64 %0, {%1,%2};" : "=l"(r) : "f"(lo), "f"(hi)); return r;
}
__device__ __forceinline__ ull ffma2(ull a, ull b, ull c) {
    ull d; asm("fma.rn.f32x2 %0, %1, %2, %3;" : "=l"(d) : "l"(a), "l"(b), "l"(c)); return d;
}
__device__ __forceinline__ ull fmul2(ull a, ull b) {
    ull d; asm("mul.rn.f32x2 %0, %1, %2;" : "=l"(d) : "l"(a), "l"(b)); return d;
}
// (re,im) -> (-im, re)   [multiply by i]
__device__ __forceinline__ ull tconj(ull a) {
    unsigned lo = (unsigned)a;            // re
    unsigned hi = (unsigned)(a >> 32);    // im
    unsigned nlo = hi ^ 0x80000000u;      // -im
    return ((ull)lo << 32) | (ull)nlo;
}

struct PG { ull pax, pay, pbx, pby, pnbx, pnay; };

// SU(2) gate [[a,-conj(b)],[b,conj(a)]] applied to amplitude pair (va, vb)
__device__ __forceinline__ void su2(const PG& g, ull& va, ull& vb) {
    ull Ta = tconj(va), Tb = tconj(vb);
    ull na = ffma2(g.pax, va, ffma2(g.pay, Ta, ffma2(g.pnbx, vb, fmul2(g.pby, Tb))));
    ull nb = ffma2(g.pbx, va, ffma2(g.pby, Ta, ffma2(g.pax, vb, fmul2(g.pnay, Tb))));
    va = na; vb = nb;
}

__device__ __forceinline__ unsigned padidx(unsigned i) { return i + (i >> 4); }

// ---------------- pass application (NW = 2 or 4 gates) ----------------
template <int NW>
__device__ __forceinline__ void apply_pass(ull* st, const float4* gates4,
                                           const PassP& pp, int tid) {
    const int NA = 1 << NW;                 // amps per group
    const int NGROUP = NSTATE / NA;

    PG G[NW];
    #pragma unroll
    for (int k = 0; k < NW; k++) {
        float4 gg = gates4[pp.g[k]];
        G[k].pax  = pack2( gg.x,  gg.x);
        G[k].pay  = pack2( gg.y,  gg.y);
        G[k].pbx  = pack2( gg.z,  gg.z);
        G[k].pby  = pack2( gg.w,  gg.w);
        G[k].pnbx = pack2(-gg.z, -gg.z);
        G[k].pnay = pack2(-gg.y, -gg.y);
    }
    const int b0 = pp.piv[0], b1 = pp.piv[1];
    const int b2 = (NW == 4) ? pp.piv[2] : 0;
    const int b3 = (NW == 4) ? pp.piv[3] : 0;

    #pragma unroll 1
    for (int q = tid; q < NGROUP; q += TPB) {
        // insert zeros at sorted pivot bits -> coset representative
        unsigned p = (unsigned)q;
        p = ((p >> b0) << (b0 + 1)) | (p & ((1u << b0) - 1u));
        p = ((p >> b1) << (b1 + 1)) | (p & ((1u << b1) - 1u));
        if (NW == 4) {
            p = ((p >> b2) << (b2 + 1)) | (p & ((1u << b2) - 1u));
            p = ((p >> b3) << (b3 + 1)) | (p & ((1u << b3) - 1u));
        }
        // parity-fold: force all logical bits of representative to 0
        #pragma unroll
        for (int k = 0; k < NW; k++)
            p ^= (unsigned)(-(int)(__popc(p & pp.r[k]) & 1)) & pp.cm[1 << k];

        unsigned addr[NA];
        ull v[NA];
        #pragma unroll
        for (int j = 0; j < NA; j++) {
            addr[j] = padidx(p ^ pp.cm[j]);
            v[j] = st[addr[j]];
        }
        #pragma unroll
        for (int k = 0; k < NW; k++) {
            #pragma unroll
            for (int j = 0; j < NA; j++) {
                if ((j >> k) & 1) continue;
                su2(G[k], v[j], v[j | (1 << k)]);
            }
        }
        #pragma unroll
        for (int j = 0; j < NA; j++) st[addr[j]] = v[j];
    }
}

// complex helpers for gate build
__device__ __forceinline__ float2 cmul(float2 a, float2 b) {
    return make_float2(a.x * b.x - a.y * b.y, a.x * b.y + a.y * b.x);
}

__global__ void __launch_bounds__(TPB, 1)
qsim_kernel(const float* __restrict__ x, const float* __restrict__ wts,
            float* __restrict__ out, Params P)
{
    extern __shared__ ull st[];                       // padded state (17408 slots)
    __shared__ float4 gates4[NGATES];                 // (alpha.x, alpha.y, beta.x, beta.y)
    __shared__ float  red[TPB / 32];

    const int tid = threadIdx.x;
    const int b   = blockIdx.x;

    // ---- build SU(2) gates: alpha = cos(t/2) e^{-i(phi+om)/2}, beta = sin(t/2) e^{-i(phi-om)/2} ----
    if (tid < NGATES) {
        int l = tid / NQ, w = tid % NQ;
        const float* ww = wts + tid * 3;
        float phi = ww[0], th = ww[1], om = ww[2];
        float stt, ct, sA, cA, sB, cB;
        sincosf(0.5f * th, &stt, &ct);
        sincosf(0.5f * (phi + om), &sA, &cA);
        sincosf(0.5f * (phi - om), &sB, &cB);
        float2 al = make_float2(ct * cA, -ct * sA);
        float2 be = make_float2(stt * cB, -stt * sB);
        if (l == 0) {
            // merge RX(x_w):  G = Rot * RX,  RX: alphaX=(c,0), betaX=(0,-s)
            float s, c;
            sincosf(0.5f * x[b * NQ + w], &s, &c);
            float2 aX = make_float2(c, 0.f), bX = make_float2(0.f, -s);
            float2 cbe = make_float2(be.x, -be.y);   // conj(beta)
            float2 cal = make_float2(al.x, -al.y);   // conj(alpha)
            float2 t1 = cmul(al, aX), t2 = cmul(cbe, bX);
            float2 aG = make_float2(t1.x - t2.x, t1.y - t2.y);
            float2 t3 = cmul(be, aX), t4 = cmul(cal, bX);
            float2 bG = make_float2(t3.x + t4.x, t3.y + t4.y);
            al = aG; be = bG;
        }
        gates4[tid] = make_float4(al.x, al.y, be.x, be.y);
    }

    // ---- init |0...0> ----
    for (int i = tid; i < NSTATE; i += TPB)
        st[padidx((unsigned)i)] = (i == 0) ? 0x3f800000ull : 0ull;  // (1.0f, 0.0f)
    __syncthreads();

    // ---- 24 passes ----
    #pragma unroll 1
    for (int ps = 0; ps < NPASSES; ps++) {
        const PassP& pp = P.p[ps];
        if (pp.nw == 4) apply_pass<4>(st, gates4, pp, tid);
        else            apply_pass<2>(st, gates4, pp, tid);
        __syncthreads();
    }

    // ---- <Z_0> ----
    float acc = 0.f;
    const unsigned rz = P.rz;
    for (int i = tid; i < NSTATE; i += TPB) {
        ull a = st[padidx((unsigned)i)];
        float re = __uint_as_float((unsigned)a);
        float im = __uint_as_float((unsigned)(a >> 32));
        float pr = fmaf(re, re, im * im);
        acc += (__popc((unsigned)i & rz) & 1) ? -pr : pr;
    }
    #pragma unroll
    for (int off = 16; off; off >>= 1)
        acc += __shfl_down_sync(0xffffffffu, acc, off);
    if ((tid & 31) == 0) red[tid >> 5] = acc;
    __syncthreads();
    if (tid == 0) {
        float s = 0.f;
        #pragma unroll
        for (int wgi = 0; wgi < TPB / 32; wgi++) s += red[wgi];
        out[b] = s;
    }
}

// ---------------- host precompute ----------------
static inline int ctz32(unsigned v) {
    int c = 0; while (!(v & 1u)) { v >>= 1; c++; } return c;
}

static void fill_pass(PassP& ps, const unsigned* col, const unsigned* row,
                      const int* wsel, int nw, int l) {
    unsigned m[4];
    for (int i = 0; i < nw; i++) {
        m[i]    = col[wsel[i]];
        ps.r[i] = row[wsel[i]];
        ps.g[i] = l * NQ + wsel[i];
    }
    int na = 1 << nw;
    for (int j = 0; j < 16; j++) ps.cm[j] = 0;
    for (int j = 0; j < na; j++) {
        unsigned c = 0;
        for (int i = 0; i < nw; i++) if ((j >> i) & 1) c ^= m[i];
        ps.cm[j] = c;
    }
    // pivots via Gaussian elimination
    unsigned redm[4]; int pv[4];
    for (int i = 0; i < nw; i++) {
        unsigned v = m[i];
        for (int j = 0; j < i; j++)
            if ((v >> pv[j]) & 1u) v ^= redm[j];
        pv[i] = ctz32(v);
        redm[i] = v;
    }
    // sort ascending
    for (int i = 0; i < nw; i++)
        for (int j = i + 1; j < nw; j++)
            if (pv[j] < pv[i]) { int t = pv[i]; pv[i] = pv[j]; pv[j] = t; }
    for (int i = 0; i < 4; i++) ps.piv[i] = (i < nw) ? pv[i] : 0;
    ps.nw = nw;
}

extern "C" void kernel_launch(void* const* d_in, const int* in_sizes, int n_in,
                              void* d_out, int out_size) {
    const float* x   = (const float*)d_in[0];
    const float* wts = (const float*)d_in[1];
    float*       out = (float*)d_out;
    const int B = in_sizes[0] / NQ;

    Params P;
    unsigned col[NQ], row[NQ];
    for (int i = 0; i < NQ; i++) { col[i] = 1u << i; row[i] = 1u << i; }

    int pi = 0;
    for (int l = 0; l < NLAYERS; l++) {
        static const int quads[3][4] = {{0,1,2,3},{4,5,6,7},{8,9,10,11}};
        for (int qq = 0; qq < 3; qq++)
            fill_pass(P.p[pi++], col, row, quads[qq], 4, l);
        static const int pairw[2] = {12, 13};
        fill_pass(P.p[pi++], col, row, pairw, 2, l);

        int r = (l % (NQ - 1)) + 1;
        for (int w = 0; w < NQ; w++) {
            int c = w, t = (w + r) % NQ;
            col[c] ^= col[t];
            row[t] ^= row[c];
        }
    }
    P.rz = row[0];

    const size_t smem = (NSTATE + NSTATE / 16) * sizeof(ull);  // 139264 B
    cudaFuncSetAttribute(qsim_kernel, cudaFuncAttributeMaxDynamicSharedMemorySize,
                         (int)smem);
    qsim_kernel<<<B, TPB, smem>>>(x, wts, out, P);
}

// round 5
// speedup vs baseline: 1.7283x; 1.0174x over previous
#include <cuda_runtime.h>
#include <cstdint>

#define NQ      14
#define NSTATE  (1 << NQ)          // 16384
#define NLAYERS 6
#define NGATES  (NLAYERS * NQ)     // 84 (RX merged into layer-0 Rot)
#define NPASSES (NLAYERS * 4)      // 24: per layer 3 quads + 1 pair
#define TPB     512

typedef unsigned long long ull;

struct PassP {
    unsigned cm[16];   // XOR masks for logical nibble j (cm[1<<i] = m_i)
    unsigned r[4];     // parity rows (L^-1)
    unsigned A[4];     // stagger matrix columns (lane bit b -> NW-bit relabel)
    int      piv[4];   // sorted pivot bits (ascending); only first nw used
    int      g[4];     // gate ids
    int      nw;       // 4 or 2
};
struct Params {
    PassP p[NPASSES];
    unsigned rz;
};

// ---------------- packed f32x2 helpers ----------------
__device__ __forceinline__ ull pack2(float lo, float hi) {
    ull r; asm("mov.b64 %0, {%1,%2};" : "=l"(r) : "f"(lo), "f"(hi)); return r;
}
__device__ __forceinline__ ull ffma2(ull a, ull b, ull c) {
    ull d; asm("fma.rn.f32x2 %0, %1, %2, %3;" : "=l"(d) : "l"(a), "l"(b), "l"(c)); return d;
}
__device__ __forceinline__ ull fmul2(ull a, ull b) {
    ull d; asm("mul.rn.f32x2 %0, %1, %2;" : "=l"(d) : "l"(a), "l"(b)); return d;
}
// (re,im) -> (-im, re)   [multiply by i]
__device__ __forceinline__ ull tconj(ull a) {
    unsigned lo = (unsigned)a;            // re
    unsigned hi = (unsigned)(a >> 32);    // im
    unsigned nlo = hi ^ 0x80000000u;      // -im
    return ((ull)lo << 32) | (ull)nlo;
}

// 6 packed coeffs; orientation (rl bit) folded in at build time.
struct PG { ull pax, pby, pc2, pc3, pc5, pc8; };

// generic SU(2) step: na = ax*va + c2*Ta + c3*vb + by*Tb
//                     nb = c5*va + by*Ta + ax*vb + c8*Tb
__device__ __forceinline__ void su2(const PG& g, ull& va, ull& vb) {
    ull Ta = tconj(va), Tb = tconj(vb);
    ull na = ffma2(g.pax, va, ffma2(g.pc2, Ta, ffma2(g.pc3, vb, fmul2(g.pby, Tb))));
    ull nb = ffma2(g.pc5, va, ffma2(g.pby, Ta, ffma2(g.pax, vb, fmul2(g.pc8, Tb))));
    va = na; vb = nb;
}

// ---------------- pass application (NW = 2 or 4 gates) ----------------
template <int NW>
__device__ __forceinline__ void apply_pass(ull* st, const float4* gates4,
                                           const PassP& pp, int tid) {
    const int NA = 1 << NW;                 // amps per group
    const int NGROUP = NSTATE / NA;

    // ---- per-lane relabel rl = A . lane4, and its coset offset cm[rl] ----
    const unsigned l4 = (unsigned)tid & 15u;
    unsigned rl = 0;
    #pragma unroll
    for (int b = 0; b < 4; b++)
        if ((l4 >> b) & 1u) rl ^= pp.A[b];
    unsigned cofs = 0;
    #pragma unroll
    for (int k = 0; k < NW; k++)
        if ((rl >> k) & 1u) cofs ^= pp.cm[1 << k];

    // ---- gate coefficients with orientation folded (flip if rl bit set) ----
    PG G[NW];
    #pragma unroll
    for (int k = 0; k < NW; k++) {
        float4 gg = gates4[pp.g[k]];        // (ax, ay, bx, by)
        bool fl = (rl >> k) & 1u;
        float ax = gg.x, ay = gg.y, bx = gg.z, by = gg.w;
        float c2 = fl ? -ay : ay;
        float c3 = fl ?  bx : -bx;
        G[k].pax = pack2(ax, ax);
        G[k].pby = pack2(by, by);
        G[k].pc2 = pack2(c2, c2);
        G[k].pc3 = pack2(c3, c3);
        G[k].pc5 = pack2(-c3, -c3);
        G[k].pc8 = pack2(-c2, -c2);
    }

    const int b0 = pp.piv[0], b1 = pp.piv[1];
    const int b2 = (NW == 4) ? pp.piv[2] : 0;
    const int b3 = (NW == 4) ? pp.piv[3] : 0;

    #pragma unroll 1
    for (int q = tid; q < NGROUP; q += TPB) {
        // insert zeros at sorted pivot bits -> coset representative
        unsigned p = (unsigned)q;
        p = ((p >> b0) << (b0 + 1)) | (p & ((1u << b0) - 1u));
        p = ((p >> b1) << (b1 + 1)) | (p & ((1u << b1) - 1u));
        if (NW == 4) {
            p = ((p >> b2) << (b2 + 1)) | (p & ((1u << b2) - 1u));
            p = ((p >> b3) << (b3 + 1)) | (p & ((1u << b3) - 1u));
        }
        // parity-fold: force all logical bits of representative to 0
        #pragma unroll
        for (int k = 0; k < NW; k++)
            p ^= (unsigned)(-(int)(__popc(p & pp.r[k]) & 1)) & pp.cm[1 << k];
        // stagger: this thread's slot s holds logical index s ^ rl
        p ^= cofs;

        unsigned addr[NA];
        ull v[NA];
        #pragma unroll
        for (int j = 0; j < NA; j++) {
            addr[j] = p ^ pp.cm[j];
            v[j] = st[addr[j]];
        }
        #pragma unroll
        for (int k = 0; k < NW; k++) {
            #pragma unroll
            for (int j = 0; j < NA; j++) {
                if ((j >> k) & 1) continue;
                su2(G[k], v[j], v[j | (1 << k)]);
            }
        }
        #pragma unroll
        for (int j = 0; j < NA; j++) st[addr[j]] = v[j];
    }
}

// complex helper for gate build
__device__ __forceinline__ float2 cmul(float2 a, float2 b) {
    return make_float2(a.x * b.x - a.y * b.y, a.x * b.y + a.y * b.x);
}

__global__ void __launch_bounds__(TPB, 1)
qsim_kernel(const float* __restrict__ x, const float* __restrict__ wts,
            float* __restrict__ out, Params P)
{
    extern __shared__ ull st[];                       // 16384 amplitudes (no padding)
    __shared__ float4 gates4[NGATES];                 // (alpha.x, alpha.y, beta.x, beta.y)
    __shared__ float  red[TPB / 32];

    const int tid = threadIdx.x;
    const int b   = blockIdx.x;

    // ---- build SU(2) gates: alpha = cos(t/2) e^{-i(phi+om)/2}, beta = sin(t/2) e^{-i(phi-om)/2} ----
    if (tid < NGATES) {
        int l = tid / NQ, w = tid % NQ;
        const float* ww = wts + tid * 3;
        float phi = ww[0], th = ww[1], om = ww[2];
        float stt, ct, sA, cA, sB, cB;
        sincosf(0.5f * th, &stt, &ct);
        sincosf(0.5f * (phi + om), &sA, &cA);
        sincosf(0.5f * (phi - om), &sB, &cB);
        float2 al = make_float2(ct * cA, -ct * sA);
        float2 be = make_float2(stt * cB, -stt * sB);
        if (l == 0) {
            // merge RX(x_w):  G = Rot * RX,  RX: alphaX=(c,0), betaX=(0,-s)
            float s, c;
            sincosf(0.5f * x[b * NQ + w], &s, &c);
            float2 aX = make_float2(c, 0.f), bX = make_float2(0.f, -s);
            float2 cbe = make_float2(be.x, -be.y);   // conj(beta)
            float2 cal = make_float2(al.x, -al.y);   // conj(alpha)
            float2 t1 = cmul(al, aX), t2 = cmul(cbe, bX);
            float2 aG = make_float2(t1.x - t2.x, t1.y - t2.y);
            float2 t3 = cmul(be, aX), t4 = cmul(cal, bX);
            float2 bG = make_float2(t3.x + t4.x, t3.y + t4.y);
            al = aG; be = bG;
        }
        gates4[tid] = make_float4(al.x, al.y, be.x, be.y);
    }

    // ---- init |0...0> ----
    for (int i = tid; i < NSTATE; i += TPB)
        st[i] = (i == 0) ? 0x3f800000ull : 0ull;     // (1.0f, 0.0f)
    __syncthreads();

    // ---- 24 passes ----
    #pragma unroll 1
    for (int ps = 0; ps < NPASSES; ps++) {
        const PassP& pp = P.p[ps];
        if (pp.nw == 4) apply_pass<4>(st, gates4, pp, tid);
        else            apply_pass<2>(st, gates4, pp, tid);
        __syncthreads();
    }

    // ---- <Z_0> ----
    float acc = 0.f;
    const unsigned rz = P.rz;
    for (int i = tid; i < NSTATE; i += TPB) {
        ull a = st[i];
        float re = __uint_as_float((unsigned)a);
        float im = __uint_as_float((unsigned)(a >> 32));
        float pr = fmaf(re, re, im * im);
        acc += (__popc((unsigned)i & rz) & 1) ? -pr : pr;
    }
    #pragma unroll
    for (int off = 16; off; off >>= 1)
        acc += __shfl_down_sync(0xffffffffu, acc, off);
    if ((tid & 31) == 0) red[tid >> 5] = acc;
    __syncthreads();
    if (tid == 0) {
        float s = 0.f;
        #pragma unroll
        for (int wgi = 0; wgi < TPB / 32; wgi++) s += red[wgi];
        out[b] = s;
    }
}

// ---------------- host precompute ----------------
static inline int ctz32(unsigned v) {
    int c = 0; while (!(v & 1u)) { v >>= 1; c++; } return c;
}

static int rank4(const unsigned* F) {
    unsigned rows[4] = {F[0], F[1], F[2], F[3]};
    int rank = 0;
    for (int bit = 0; bit < 4; bit++) {
        int sel = -1;
        for (int r = rank; r < 4; r++) if ((rows[r] >> bit) & 1u) { sel = r; break; }
        if (sel < 0) continue;
        unsigned t = rows[sel]; rows[sel] = rows[rank]; rows[rank] = t;
        for (int r = 0; r < 4; r++)
            if (r != rank && ((rows[r] >> bit) & 1u)) rows[r] ^= rows[rank];
        rank++;
    }
    return rank;
}

static void choose_A(PassP& ps, int nw) {
    // amp-bit position of lane bit b after monotone zero-insertion
    unsigned Pcol[4];
    for (int bb = 0; bb < 4; bb++) {
        int pos = bb;
        for (int i = 0; i < nw; i++) if (ps.piv[i] <= pos) pos++;
        Pcol[bb] = (pos < 4) ? (1u << pos) : 0u;
    }
    int na = 1 << nw;
    // brute-force stagger columns A[b] in [0, na)
    for (int a0 = 0; a0 < na; a0++)
    for (int a1 = 0; a1 < na; a1++)
    for (int a2 = 0; a2 < na; a2++)
    for (int a3 = 0; a3 < na; a3++) {
        unsigned F[4] = { Pcol[0] ^ (ps.cm[a0] & 15u),
                          Pcol[1] ^ (ps.cm[a1] & 15u),
                          Pcol[2] ^ (ps.cm[a2] & 15u),
                          Pcol[3] ^ (ps.cm[a3] & 15u) };
        if (rank4(F) == 4) {
            ps.A[0] = (unsigned)a0; ps.A[1] = (unsigned)a1;
            ps.A[2] = (unsigned)a2; ps.A[3] = (unsigned)a3;
            return;
        }
    }
    ps.A[0] = ps.A[1] = ps.A[2] = ps.A[3] = 0;   // safe fallback (conflicts, still correct)
}

static void fill_pass(PassP& ps, const unsigned* col, const unsigned* row,
                      const int* wsel, int nw, int l) {
    unsigned m[4];
    for (int i = 0; i < nw; i++) {
        m[i]    = col[wsel[i]];
        ps.r[i] = row[wsel[i]];
        ps.g[i] = l * NQ + wsel[i];
    }
    int na = 1 << nw;
    for (int j = 0; j < 16; j++) ps.cm[j] = 0;
    for (int j = 0; j < na; j++) {
        unsigned c = 0;
        for (int i = 0; i < nw; i++) if ((j >> i) & 1) c ^= m[i];
        ps.cm[j] = c;
    }
    // pivots via Gaussian elimination
    unsigned redm[4]; int pv[4];
    for (int i = 0; i < nw; i++) {
        unsigned v = m[i];
        for (int j = 0; j < i; j++)
            if ((v >> pv[j]) & 1u) v ^= redm[j];
        pv[i] = ctz32(v);
        redm[i] = v;
    }
    for (int i = 0; i < nw; i++)
        for (int j = i + 1; j < nw; j++)
            if (pv[j] < pv[i]) { int t = pv[i]; pv[i] = pv[j]; pv[j] = t; }
    for (int i = 0; i < 4; i++) ps.piv[i] = (i < nw) ? pv[i] : 0;
    ps.nw = nw;
    choose_A(ps, nw);
}

extern "C" void kernel_launch(void* const* d_in, const int* in_sizes, int n_in,
                              void* d_out, int out_size) {
    const float* x   = (const float*)d_in[0];
    const float* wts = (const float*)d_in[1];
    float*       out = (float*)d_out;
    const int B = in_sizes[0] / NQ;

    Params P;
    unsigned col[NQ], row[NQ];
    for (int i = 0; i < NQ; i++) { col[i] = 1u << i; row[i] = 1u << i; }

    int pi = 0;
    for (int l = 0; l < NLAYERS; l++) {
        static const int quads[3][4] = {{0,1,2,3},{4,5,6,7},{8,9,10,11}};
        for (int qq = 0; qq < 3; qq++)
            fill_pass(P.p[pi++], col, row, quads[qq], 4, l);
        static const int pairw[2] = {12, 13};
        fill_pass(P.p[pi++], col, row, pairw, 2, l);

        int r = (l % (NQ - 1)) + 1;
        for (int w = 0; w < NQ; w++) {
            int c = w, t = (w + r) % NQ;
            col[c] ^= col[t];
            row[t] ^= row[c];
        }
    }
    P.rz = row[0];

    const size_t smem = NSTATE * sizeof(ull);   // 131072 B, no padding
    cudaFuncSetAttribute(qsim_kernel, cudaFuncAttributeMaxDynamicSharedMemorySize,
                         (int)smem);
    qsim_kernel<<<B, TPB, smem>>>(x, wts, out, P);
}